// round 1
// baseline (speedup 1.0000x reference)
#include <cuda_runtime.h>
#include <math.h>

#define NG    4096
#define NB    16
#define SS    4
#define RES   64
#define CAP   512
#define RELAX 0.1875f   // block_size * relax_ratio = (2/16)*1.5

// ---- scratch (SoA for coalesced cull scan) ----
__device__ float g_px[NG], g_py[NG], g_pz[NG];
__device__ float g_i0[NG], g_i1[NG], g_i2[NG], g_i3[NG], g_i4[NG], g_i5[NG];
__device__ float g_w[NG];
__device__ float g_center[3];
__device__ float g_scale;

// ============================================================
// Kernel 1: opacity keep-mask + min/max -> center, scale
// ============================================================
__global__ void kstats(const float* __restrict__ xyz, const float* __restrict__ opac) {
    __shared__ float red[6][256];
    int t = threadIdx.x;
    float mn0 = 1e10f, mn1 = 1e10f, mn2 = 1e10f;
    float mx0 = -1e10f, mx1 = -1e10f, mx2 = -1e10f;
    for (int g = t; g < NG; g += 256) {
        float o   = opac[g];
        float sig = 1.0f / (1.0f + expf(-o));
        if (sig > 0.005f) {
            float x = xyz[3 * g], y = xyz[3 * g + 1], z = xyz[3 * g + 2];
            mn0 = fminf(mn0, x); mn1 = fminf(mn1, y); mn2 = fminf(mn2, z);
            mx0 = fmaxf(mx0, x); mx1 = fmaxf(mx1, y); mx2 = fmaxf(mx2, z);
        }
    }
    red[0][t] = mn0; red[1][t] = mn1; red[2][t] = mn2;
    red[3][t] = mx0; red[4][t] = mx1; red[5][t] = mx2;
    __syncthreads();
    for (int s = 128; s > 0; s >>= 1) {
        if (t < s) {
            red[0][t] = fminf(red[0][t], red[0][t + s]);
            red[1][t] = fminf(red[1][t], red[1][t + s]);
            red[2][t] = fminf(red[2][t], red[2][t + s]);
            red[3][t] = fmaxf(red[3][t], red[3][t + s]);
            red[4][t] = fmaxf(red[4][t], red[4][t + s]);
            red[5][t] = fmaxf(red[5][t], red[5][t + s]);
        }
        __syncthreads();
    }
    if (t == 0) {
        g_center[0] = (red[0][0] + red[3][0]) * 0.5f;
        g_center[1] = (red[1][0] + red[4][0]) * 0.5f;
        g_center[2] = (red[2][0] + red[5][0]) * 0.5f;
        float ext = fmaxf(fmaxf(red[3][0] - red[0][0], red[4][0] - red[1][0]),
                          red[5][0] - red[2][0]);
        g_scale = 1.8f / ext;
    }
}

// ============================================================
// Kernel 2: per-gaussian normalized xyz + inverse covariance + opacity
// ============================================================
__global__ void kprep(const float* __restrict__ xyz, const float* __restrict__ scaling,
                      const float* __restrict__ rot, const float* __restrict__ opac) {
    int g = blockIdx.x * blockDim.x + threadIdx.x;
    if (g >= NG) return;

    float sc = g_scale;
    g_px[g] = (xyz[3 * g]     - g_center[0]) * sc;
    g_py[g] = (xyz[3 * g + 1] - g_center[1]) * sc;
    g_pz[g] = (xyz[3 * g + 2] - g_center[2]) * sc;

    float o   = opac[g];
    float sig = 1.0f / (1.0f + expf(-o));
    g_w[g] = (sig > 0.005f) ? sig : 0.0f;

    float s0 = expf(scaling[3 * g])     * sc;
    float s1 = expf(scaling[3 * g + 1]) * sc;
    float s2 = expf(scaling[3 * g + 2]) * sc;

    float r = rot[4 * g], x = rot[4 * g + 1], y = rot[4 * g + 2], z = rot[4 * g + 3];
    float n = sqrtf(r * r + x * x + y * y + z * z);
    r /= n; x /= n; y /= n; z /= n;

    // rotation matrix
    float R00 = 1.0f - 2.0f * (y * y + z * z);
    float R01 = 2.0f * (x * y - r * z);
    float R02 = 2.0f * (x * z + r * y);
    float R10 = 2.0f * (x * y + r * z);
    float R11 = 1.0f - 2.0f * (x * x + z * z);
    float R12 = 2.0f * (y * z - r * x);
    float R20 = 2.0f * (x * z - r * y);
    float R21 = 2.0f * (y * z + r * x);
    float R22 = 1.0f - 2.0f * (x * x + y * y);

    // L = R * diag(stds); C = L L^T
    float L00 = R00 * s0, L01 = R01 * s1, L02 = R02 * s2;
    float L10 = R10 * s0, L11 = R11 * s1, L12 = R12 * s2;
    float L20 = R20 * s0, L21 = R21 * s1, L22 = R22 * s2;

    float a = L00 * L00 + L01 * L01 + L02 * L02;  // C00
    float b = L00 * L10 + L01 * L11 + L02 * L12;  // C01
    float c = L00 * L20 + L01 * L21 + L02 * L22;  // C02
    float d = L10 * L10 + L11 * L11 + L12 * L12;  // C11
    float e = L10 * L20 + L11 * L21 + L12 * L22;  // C12
    float f = L20 * L20 + L21 * L21 + L22 * L22;  // C22

    float det = a * d * f + 2.0f * e * c * b - e * e * a - c * c * d - b * b * f + 1e-24f;
    float id  = 1.0f / det;
    g_i0[g] = (d * f - e * e) * id;  // inv_a  (dx*dx)
    g_i1[g] = (e * c - b * f) * id;  // inv_b  (dx*dy)
    g_i2[g] = (e * b - c * d) * id;  // inv_c  (dx*dz)
    g_i3[g] = (a * f - c * c) * id;  // inv_d  (dy*dy)
    g_i4[g] = (b * c - e * a) * id;  // inv_e  (dy*dz)
    g_i5[g] = (a * d - b * b) * id;  // inv_f  (dz*dz)
}

// ============================================================
// Kernel 3: one CTA per 4x4x4 spatial block; cull + accumulate
// ============================================================
__device__ __forceinline__ float accum_range(
    int cnt, float px, float py, float pz,
    const float* __restrict__ sx, const float* __restrict__ sy, const float* __restrict__ sz,
    const float* __restrict__ s0, const float* __restrict__ s1, const float* __restrict__ s2,
    const float* __restrict__ s3, const float* __restrict__ s4, const float* __restrict__ s5,
    const float* __restrict__ sw)
{
    float acc = 0.0f;
    for (int j = 0; j < cnt; j++) {
        float dx = px - sx[j], dy = py - sy[j], dz = pz - sz[j];
        float p = -0.5f * (dx * dx * s0[j] + dy * dy * s3[j] + dz * dz * s5[j])
                  - dx * dy * s1[j] - dx * dz * s2[j] - dy * dz * s4[j];
        if (p <= 0.0f) acc += sw[j] * __expf(p);
    }
    return acc;
}

__global__ void __launch_bounds__(64) kmain(float* __restrict__ out) {
    __shared__ float sx[CAP], sy[CAP], sz[CAP];
    __shared__ float s0[CAP], s1[CAP], s2[CAP], s3[CAP], s4[CAP], s5[CAP];
    __shared__ float sw[CAP];
    __shared__ int   warp_cnt[2];

    const int b  = blockIdx.x;
    const int bi = b >> 8, bj = (b >> 4) & 15, bk = b & 15;
    const int t  = threadIdx.x;
    const int lane = t & 31, w = t >> 5;

    const float step = 2.0f / 63.0f;
    const float xmin = -1.0f + step * (float)(bi * SS)          - RELAX;
    const float xmax = -1.0f + step * (float)(bi * SS + SS - 1) + RELAX;
    const float ymin = -1.0f + step * (float)(bj * SS)          - RELAX;
    const float ymax = -1.0f + step * (float)(bj * SS + SS - 1) + RELAX;
    const float zmin = -1.0f + step * (float)(bk * SS)          - RELAX;
    const float zmax = -1.0f + step * (float)(bk * SS + SS - 1) + RELAX;

    const int oi = t >> 4, oj = (t >> 2) & 3, ok = t & 3;
    const float px = -1.0f + step * (float)(bi * SS + oi);
    const float py = -1.0f + step * (float)(bj * SS + oj);
    const float pz = -1.0f + step * (float)(bk * SS + ok);

    float acc = 0.0f;
    int cnt = 0;  // uniform across CTA

    for (int base = 0; base < NG; base += 64) {
        int g = base + t;
        float gx = g_px[g], gy = g_py[g], gz = g_pz[g];
        float gw = g_w[g];
        bool pass = (gw > 0.0f) &&
                    (gx > xmin) && (gx < xmax) &&
                    (gy > ymin) && (gy < ymax) &&
                    (gz > zmin) && (gz < zmax);
        unsigned m = __ballot_sync(0xffffffffu, pass);
        if (lane == 0) warp_cnt[w] = __popc(m);
        __syncthreads();
        int c0 = warp_cnt[0], c1 = warp_cnt[1];
        int total = c0 + c1;

        if (cnt + total > CAP) {
            // flush: accumulate current buffer, then reset
            acc += accum_range(cnt, px, py, pz, sx, sy, sz, s0, s1, s2, s3, s4, s5, sw);
            cnt = 0;
            __syncthreads();  // all reads done before slots get overwritten
        }

        if (pass) {
            int pos = cnt + (w ? c0 : 0) + __popc(m & ((1u << lane) - 1u));
            sx[pos] = gx; sy[pos] = gy; sz[pos] = gz; sw[pos] = gw;
            s0[pos] = g_i0[g]; s1[pos] = g_i1[g]; s2[pos] = g_i2[g];
            s3[pos] = g_i3[g]; s4[pos] = g_i4[g]; s5[pos] = g_i5[g];
        }
        cnt += total;
        __syncthreads();  // writes visible; warp_cnt safe to overwrite next iter
    }

    acc += accum_range(cnt, px, py, pz, sx, sy, sz, s0, s1, s2, s3, s4, s5, sw);

    const int gx_i = bi * SS + oi, gy_i = bj * SS + oj, gz_i = bk * SS + ok;
    out[(gx_i * RES + gy_i) * RES + gz_i] = acc;
}

// ============================================================
extern "C" void kernel_launch(void* const* d_in, const int* in_sizes, int n_in,
                              void* d_out, int out_size) {
    const float* xyz     = (const float*)d_in[0];
    const float* scaling = (const float*)d_in[1];
    const float* rot     = (const float*)d_in[2];
    const float* opac    = (const float*)d_in[3];
    float* out = (float*)d_out;

    kstats<<<1, 256>>>(xyz, opac);
    kprep<<<NG / 256, 256>>>(xyz, scaling, rot, opac);
    kmain<<<NB * NB * NB, 64>>>(out);
}

// round 2
// speedup vs baseline: 2.2003x; 2.2003x over previous
#include <cuda_runtime.h>
#include <math.h>

#define NG     4096
#define NB     16
#define SS     4
#define RES    64
#define CHUNK  256
#define RELAX  0.1875f             // (2/16)*1.5
#define STEP   (2.0f/63.0f)
#define LOG2E  1.4426950408889634f

// ---- scratch ----
__device__ float4   g_par[NG * 3];          // (cx,cy,cz,w) (q0,q1,q2,q3) (q4,q5,_,_)
__device__ unsigned g_mask[3][NB][NG / 32]; // per-axis, per-slot occupancy bitmask

// ============================================================
// Kernel A (1 CTA, 1024 thr): stats reduce + per-gaussian prep + axis masks
// ============================================================
__global__ void __launch_bounds__(1024) kA(const float* __restrict__ xyz,
                                           const float* __restrict__ scaling,
                                           const float* __restrict__ rot,
                                           const float* __restrict__ opac) {
    __shared__ float rmn[32][3], rmx[32][3];
    __shared__ float bc[4];
    const int t = threadIdx.x, lane = t & 31, wi = t >> 5;

    // ---- phase 1: sigmoid + masked min/max ----
    float sig4[4];
    float mn0 = 1e10f, mn1 = 1e10f, mn2 = 1e10f;
    float mx0 = -1e10f, mx1 = -1e10f, mx2 = -1e10f;
#pragma unroll
    for (int i = 0; i < 4; i++) {
        int g = i * 1024 + t;
        float o = opac[g];
        float s = 1.0f / (1.0f + expf(-o));
        sig4[i] = s;
        float x = xyz[3 * g], y = xyz[3 * g + 1], z = xyz[3 * g + 2];
        if (s > 0.005f) {
            mn0 = fminf(mn0, x); mn1 = fminf(mn1, y); mn2 = fminf(mn2, z);
            mx0 = fmaxf(mx0, x); mx1 = fmaxf(mx1, y); mx2 = fmaxf(mx2, z);
        }
    }
#pragma unroll
    for (int s = 16; s; s >>= 1) {
        mn0 = fminf(mn0, __shfl_xor_sync(0xffffffffu, mn0, s));
        mn1 = fminf(mn1, __shfl_xor_sync(0xffffffffu, mn1, s));
        mn2 = fminf(mn2, __shfl_xor_sync(0xffffffffu, mn2, s));
        mx0 = fmaxf(mx0, __shfl_xor_sync(0xffffffffu, mx0, s));
        mx1 = fmaxf(mx1, __shfl_xor_sync(0xffffffffu, mx1, s));
        mx2 = fmaxf(mx2, __shfl_xor_sync(0xffffffffu, mx2, s));
    }
    if (lane == 0) {
        rmn[wi][0] = mn0; rmn[wi][1] = mn1; rmn[wi][2] = mn2;
        rmx[wi][0] = mx0; rmx[wi][1] = mx1; rmx[wi][2] = mx2;
    }
    __syncthreads();
    if (wi == 0) {
        float a0 = rmn[lane][0], a1 = rmn[lane][1], a2 = rmn[lane][2];
        float b0 = rmx[lane][0], b1 = rmx[lane][1], b2 = rmx[lane][2];
#pragma unroll
        for (int s = 16; s; s >>= 1) {
            a0 = fminf(a0, __shfl_xor_sync(0xffffffffu, a0, s));
            a1 = fminf(a1, __shfl_xor_sync(0xffffffffu, a1, s));
            a2 = fminf(a2, __shfl_xor_sync(0xffffffffu, a2, s));
            b0 = fmaxf(b0, __shfl_xor_sync(0xffffffffu, b0, s));
            b1 = fmaxf(b1, __shfl_xor_sync(0xffffffffu, b1, s));
            b2 = fmaxf(b2, __shfl_xor_sync(0xffffffffu, b2, s));
        }
        if (lane == 0) {
            bc[0] = (a0 + b0) * 0.5f;
            bc[1] = (a1 + b1) * 0.5f;
            bc[2] = (a2 + b2) * 0.5f;
            bc[3] = 1.8f / fmaxf(fmaxf(b0 - a0, b1 - a1), b2 - a2);
        }
    }
    __syncthreads();
    const float cx = bc[0], cy = bc[1], cz = bc[2], sc = bc[3];

    // ---- phase 2: prep params + axis masks ----
#pragma unroll 1
    for (int i = 0; i < 4; i++) {
        int g = i * 1024 + t;
        float gx = (xyz[3 * g]     - cx) * sc;
        float gy = (xyz[3 * g + 1] - cy) * sc;
        float gz = (xyz[3 * g + 2] - cz) * sc;
        float w  = (sig4[i] > 0.005f) ? sig4[i] : 0.0f;

        float s0 = expf(scaling[3 * g])     * sc;
        float s1 = expf(scaling[3 * g + 1]) * sc;
        float s2 = expf(scaling[3 * g + 2]) * sc;

        float r = rot[4 * g], x = rot[4 * g + 1], y = rot[4 * g + 2], z = rot[4 * g + 3];
        float rn = 1.0f / sqrtf(r * r + x * x + y * y + z * z);
        r *= rn; x *= rn; y *= rn; z *= rn;

        float R00 = 1.0f - 2.0f * (y * y + z * z);
        float R01 = 2.0f * (x * y - r * z);
        float R02 = 2.0f * (x * z + r * y);
        float R10 = 2.0f * (x * y + r * z);
        float R11 = 1.0f - 2.0f * (x * x + z * z);
        float R12 = 2.0f * (y * z - r * x);
        float R20 = 2.0f * (x * z - r * y);
        float R21 = 2.0f * (y * z + r * x);
        float R22 = 1.0f - 2.0f * (x * x + y * y);

        float L00 = R00 * s0, L01 = R01 * s1, L02 = R02 * s2;
        float L10 = R10 * s0, L11 = R11 * s1, L12 = R12 * s2;
        float L20 = R20 * s0, L21 = R21 * s1, L22 = R22 * s2;

        float a = L00 * L00 + L01 * L01 + L02 * L02;
        float b = L00 * L10 + L01 * L11 + L02 * L12;
        float c = L00 * L20 + L01 * L21 + L02 * L22;
        float d = L10 * L10 + L11 * L11 + L12 * L12;
        float e = L10 * L20 + L11 * L21 + L12 * L22;
        float f = L20 * L20 + L21 * L21 + L22 * L22;

        float det = a * d * f + 2.0f * e * c * b - e * e * a - c * c * d - b * b * f + 1e-24f;
        float id  = 1.0f / det;
        // prescale: fold -0.5 (diag), -1 (offdiag) and log2(e) into the coeffs
        float q0 = (d * f - e * e) * id * (-0.5f * LOG2E);
        float q1 = (e * c - b * f) * id * (-LOG2E);
        float q2 = (e * b - c * d) * id * (-LOG2E);
        float q3 = (a * f - c * c) * id * (-0.5f * LOG2E);
        float q4 = (b * c - e * a) * id * (-LOG2E);
        float q5 = (a * d - b * b) * id * (-0.5f * LOG2E);

        g_par[3 * g]     = make_float4(gx, gy, gz, w);
        g_par[3 * g + 1] = make_float4(q0, q1, q2, q3);
        g_par[3 * g + 2] = make_float4(q4, q5, 0.0f, 0.0f);

        // axis masks: warp wi of iter i owns gaussians [1024i+32wi, +32)
        int word = 32 * i + wi;
#pragma unroll 1
        for (int s = 0; s < 16; s++) {
            float lo = -1.0f + STEP * (float)(s * SS)          - RELAX;
            float hi = -1.0f + STEP * (float)(s * SS + SS - 1) + RELAX;
            unsigned bx = __ballot_sync(0xffffffffu, (w > 0.0f) && (gx > lo) && (gx < hi));
            unsigned by = __ballot_sync(0xffffffffu, (gy > lo) && (gy < hi));
            unsigned bz = __ballot_sync(0xffffffffu, (gz > lo) && (gz < hi));
            if (lane == 0) {
                g_mask[0][s][word] = bx;
                g_mask[1][s][word] = by;
                g_mask[2][s][word] = bz;
            }
        }
    }
}

// ============================================================
// Kernel B: one CTA per 4x4x4 block; mask-AND -> list -> chunked accumulate
// 256 threads = 64 points x 4 list-splits
// ============================================================
__global__ void __launch_bounds__(256) kmain(float* __restrict__ out) {
    __shared__ unsigned short list[NG];      // 8 KB
    __shared__ float4 pars[CHUNK * 3];       // 12 KB
    __shared__ int    wtot[4];
    __shared__ int    s_cnt;
    __shared__ float  red[256];

    const int b  = blockIdx.x;
    const int bi = b >> 8, bj = (b >> 4) & 15, bk = b & 15;
    const int t  = threadIdx.x, lane = t & 31, wi = t >> 5;

    // ---- mask AND + deterministic compaction (threads 0..127, one word each) ----
    unsigned m = 0; int lc = 0; int inc = 0;
    if (t < 128) {
        m  = g_mask[0][bi][t] & g_mask[1][bj][t] & g_mask[2][bk][t];
        lc = __popc(m);
        inc = lc;
#pragma unroll
        for (int s = 1; s < 32; s <<= 1) {
            int v = __shfl_up_sync(0xffffffffu, inc, s);
            if (lane >= s) inc += v;
        }
        if (lane == 31) wtot[wi] = inc;
    }
    __syncthreads();
    if (t < 128) {
        int base = 0;
#pragma unroll
        for (int k = 0; k < 3; k++) if (wi > k) base += wtot[k];
        int off = base + inc - lc;
        unsigned gb = (unsigned)t * 32u;
        unsigned mm = m;
        while (mm) {
            int bp = __ffs(mm) - 1;
            mm &= mm - 1;
            list[off++] = (unsigned short)(gb + bp);
        }
    }
    if (t == 0) s_cnt = wtot[0] + wtot[1] + wtot[2] + wtot[3];
    __syncthreads();
    const int cnt = s_cnt;

    const int pt = t & 63, sp = t >> 6;
    const int oi = pt >> 4, oj = (pt >> 2) & 3, ok = pt & 3;
    const int gxi = bi * SS + oi, gyi = bj * SS + oj, gzi = bk * SS + ok;

    if (cnt == 0) {
        if (t < 64) out[(gxi * RES + gyi) * RES + gzi] = 0.0f;
        return;
    }

    const float px = -1.0f + STEP * (float)gxi;
    const float py = -1.0f + STEP * (float)gyi;
    const float pz = -1.0f + STEP * (float)gzi;

    float acc = 0.0f;
    for (int c = 0; c < cnt; c += CHUNK) {
        int mm2 = min(CHUNK, cnt - c);
        if (t < mm2) {
            int g = list[c + t];
            pars[3 * t]     = g_par[3 * g];
            pars[3 * t + 1] = g_par[3 * g + 1];
            pars[3 * t + 2] = g_par[3 * g + 2];
        }
        __syncthreads();
#pragma unroll 2
        for (int j = sp; j < mm2; j += 4) {
            float4 A = pars[3 * j];
            float4 B = pars[3 * j + 1];
            float4 C = pars[3 * j + 2];
            float dx = px - A.x, dy = py - A.y, dz = pz - A.z;
            float t1 = fmaf(dz, B.z, fmaf(dy, B.y, dx * B.x));
            float t2 = fmaf(dz, C.x, dy * B.w);
            float u  = dz * C.y;
            float p  = fmaf(dx, t1, fmaf(dy, t2, dz * u));
            if (p <= 0.0f) acc = fmaf(A.w, exp2f(p), acc);
        }
        __syncthreads();
    }

    // combine the 4 split partials per point (deterministic order)
    red[t] = acc;
    __syncthreads();
    if (t < 64) {
        float v = ((red[t] + red[t + 64]) + red[t + 128]) + red[t + 192];
        out[(gxi * RES + gyi) * RES + gzi] = v;
    }
}

// ============================================================
extern "C" void kernel_launch(void* const* d_in, const int* in_sizes, int n_in,
                              void* d_out, int out_size) {
    const float* xyz     = (const float*)d_in[0];
    const float* scaling = (const float*)d_in[1];
    const float* rot     = (const float*)d_in[2];
    const float* opac    = (const float*)d_in[3];
    float* out = (float*)d_out;

    kA<<<1, 1024>>>(xyz, scaling, rot, opac);
    kmain<<<NB * NB * NB, 256>>>(out);
}

// round 3
// speedup vs baseline: 3.1878x; 1.4488x over previous
#include <cuda_runtime.h>
#include <math.h>

#define NG     4096
#define NB     16
#define SS     4
#define RES    64
#define RELAX  0.1875f             // (2/16)*1.5
#define STEP   (2.0f/63.0f)
#define LOG2E  1.4426950408889634f
#define NW     (NG/32)             // 128 mask words

// ---- scratch ----
__device__ float4   g_par[NG * 3];          // (cx,cy,cz,w) (q0,q1,q2,q3) (q4,q5,_,_)
__device__ unsigned g_mask[3][NB][NW];      // per-axis, per-slot occupancy bitmask

// ============================================================
// Kernel A: 128 CTAs x 128 thr.
// Every CTA redundantly computes center/scale (deterministic),
// then warp 0 preps its 32 gaussians + emits mask word b.
// ============================================================
__global__ void __launch_bounds__(128) kA(const float* __restrict__ xyz,
                                          const float* __restrict__ scaling,
                                          const float* __restrict__ rot,
                                          const float* __restrict__ opac) {
    __shared__ float wmn[4][3], wmx[4][3];
    const int t = threadIdx.x, lane = t & 31, wi = t >> 5;
    const int b = blockIdx.x;

    // ---- redundant stats: warp wi covers words [wi*32, wi*32+32) ----
    float mn0 = 1e10f, mn1 = 1e10f, mn2 = 1e10f;
    float mx0 = -1e10f, mx1 = -1e10f, mx2 = -1e10f;
#pragma unroll 4
    for (int it = 0; it < 32; it++) {
        int g = (wi * 32 + it) * 32 + lane;
        float o = opac[g];
        float s = 1.0f / (1.0f + expf(-o));
        if (s > 0.005f) {
            float x = xyz[3 * g], y = xyz[3 * g + 1], z = xyz[3 * g + 2];
            mn0 = fminf(mn0, x); mn1 = fminf(mn1, y); mn2 = fminf(mn2, z);
            mx0 = fmaxf(mx0, x); mx1 = fmaxf(mx1, y); mx2 = fmaxf(mx2, z);
        }
    }
#pragma unroll
    for (int s = 16; s; s >>= 1) {
        mn0 = fminf(mn0, __shfl_xor_sync(0xffffffffu, mn0, s));
        mn1 = fminf(mn1, __shfl_xor_sync(0xffffffffu, mn1, s));
        mn2 = fminf(mn2, __shfl_xor_sync(0xffffffffu, mn2, s));
        mx0 = fmaxf(mx0, __shfl_xor_sync(0xffffffffu, mx0, s));
        mx1 = fmaxf(mx1, __shfl_xor_sync(0xffffffffu, mx1, s));
        mx2 = fmaxf(mx2, __shfl_xor_sync(0xffffffffu, mx2, s));
    }
    if (lane == 0) {
        wmn[wi][0] = mn0; wmn[wi][1] = mn1; wmn[wi][2] = mn2;
        wmx[wi][0] = mx0; wmx[wi][1] = mx1; wmx[wi][2] = mx2;
    }
    __syncthreads();
    if (wi != 0) return;

    float a0 = 1e10f, a1 = 1e10f, a2 = 1e10f;
    float b0 = -1e10f, b1 = -1e10f, b2 = -1e10f;
#pragma unroll
    for (int k = 0; k < 4; k++) {
        a0 = fminf(a0, wmn[k][0]); a1 = fminf(a1, wmn[k][1]); a2 = fminf(a2, wmn[k][2]);
        b0 = fmaxf(b0, wmx[k][0]); b1 = fmaxf(b1, wmx[k][1]); b2 = fmaxf(b2, wmx[k][2]);
    }
    const float cx = (a0 + b0) * 0.5f;
    const float cy = (a1 + b1) * 0.5f;
    const float cz = (a2 + b2) * 0.5f;
    const float sc = 1.8f / fmaxf(fmaxf(b0 - a0, b1 - a1), b2 - a2);

    // ---- prep: gaussian g = b*32 + lane ----
    const int g = b * 32 + lane;
    float gx = (xyz[3 * g]     - cx) * sc;
    float gy = (xyz[3 * g + 1] - cy) * sc;
    float gz = (xyz[3 * g + 2] - cz) * sc;
    float o  = opac[g];
    float sig = 1.0f / (1.0f + expf(-o));
    float w  = (sig > 0.005f) ? sig : 0.0f;

    float s0 = expf(scaling[3 * g])     * sc;
    float s1 = expf(scaling[3 * g + 1]) * sc;
    float s2 = expf(scaling[3 * g + 2]) * sc;

    float r = rot[4 * g], x = rot[4 * g + 1], y = rot[4 * g + 2], z = rot[4 * g + 3];
    float rn = 1.0f / sqrtf(r * r + x * x + y * y + z * z);
    r *= rn; x *= rn; y *= rn; z *= rn;

    float R00 = 1.0f - 2.0f * (y * y + z * z);
    float R01 = 2.0f * (x * y - r * z);
    float R02 = 2.0f * (x * z + r * y);
    float R10 = 2.0f * (x * y + r * z);
    float R11 = 1.0f - 2.0f * (x * x + z * z);
    float R12 = 2.0f * (y * z - r * x);
    float R20 = 2.0f * (x * z - r * y);
    float R21 = 2.0f * (y * z + r * x);
    float R22 = 1.0f - 2.0f * (x * x + y * y);

    float L00 = R00 * s0, L01 = R01 * s1, L02 = R02 * s2;
    float L10 = R10 * s0, L11 = R11 * s1, L12 = R12 * s2;
    float L20 = R20 * s0, L21 = R21 * s1, L22 = R22 * s2;

    float a = L00 * L00 + L01 * L01 + L02 * L02;
    float bb = L00 * L10 + L01 * L11 + L02 * L12;
    float c = L00 * L20 + L01 * L21 + L02 * L22;
    float d = L10 * L10 + L11 * L11 + L12 * L12;
    float e = L10 * L20 + L11 * L21 + L12 * L22;
    float f = L20 * L20 + L21 * L21 + L22 * L22;

    float det = a * d * f + 2.0f * e * c * bb - e * e * a - c * c * d - bb * bb * f + 1e-24f;
    float id  = 1.0f / det;
    float q0 = (d * f - e * e)   * id * (-0.5f * LOG2E);
    float q1 = (e * c - bb * f)  * id * (-LOG2E);
    float q2 = (e * bb - c * d)  * id * (-LOG2E);
    float q3 = (a * f - c * c)   * id * (-0.5f * LOG2E);
    float q4 = (bb * c - e * a)  * id * (-LOG2E);
    float q5 = (a * d - bb * bb) * id * (-0.5f * LOG2E);

    g_par[3 * g]     = make_float4(gx, gy, gz, w);
    g_par[3 * g + 1] = make_float4(q0, q1, q2, q3);
    g_par[3 * g + 2] = make_float4(q4, q5, 0.0f, 0.0f);

    // ---- axis masks: this warp emits word b for all 16 slots x 3 axes ----
#pragma unroll 1
    for (int s = 0; s < 16; s++) {
        float lo = -1.0f + STEP * (float)(s * SS)          - RELAX;
        float hi = -1.0f + STEP * (float)(s * SS + SS - 1) + RELAX;
        unsigned bx = __ballot_sync(0xffffffffu, (w > 0.0f) && (gx > lo) && (gx < hi));
        unsigned by = __ballot_sync(0xffffffffu, (gy > lo) && (gy < hi));
        unsigned bz = __ballot_sync(0xffffffffu, (gz > lo) && (gz < hi));
        if (lane == 0) {
            g_mask[0][s][b] = bx;
            g_mask[1][s][b] = by;
            g_mask[2][s][b] = bz;
        }
    }
}

// ============================================================
// Kernel B: one CTA per 4x4x4 block.
// 256 threads = 16 (x,y) columns x 16 list-splits.
// Each thread evaluates a full z-column (4 pts) per gaussian:
//   p(dz) = c2*dz^2 + c1*dz + c0  (quadratic in dz)
// ============================================================
__global__ void __launch_bounds__(256) kmain(float* __restrict__ out) {
    __shared__ unsigned short list[NG];   // 8 KB
    __shared__ float red[16][64];         // 4 KB  [split][point]
    __shared__ int   wtot[4];
    __shared__ int   s_cnt;

    const int b  = blockIdx.x;
    const int bi = b >> 8, bj = (b >> 4) & 15, bk = b & 15;
    const int t  = threadIdx.x, lane = t & 31, wi = t >> 5;

    // ---- mask AND + deterministic compaction (threads 0..127) ----
    unsigned m = 0; int lc = 0; int inc = 0;
    if (t < NW) {
        m  = g_mask[0][bi][t] & g_mask[1][bj][t] & g_mask[2][bk][t];
        lc = __popc(m);
        inc = lc;
#pragma unroll
        for (int s = 1; s < 32; s <<= 1) {
            int v = __shfl_up_sync(0xffffffffu, inc, s);
            if (lane >= s) inc += v;
        }
        if (lane == 31) wtot[wi] = inc;
    }
    __syncthreads();
    if (t < NW) {
        int base = 0;
#pragma unroll
        for (int k = 0; k < 3; k++) if (wi > k) base += wtot[k];
        int off = base + inc - lc;
        unsigned gb = (unsigned)t * 32u;
        unsigned mm = m;
        while (mm) {
            int bp = __ffs(mm) - 1;
            mm &= mm - 1;
            list[off++] = (unsigned short)(gb + bp);
        }
    }
    if (t == 0) s_cnt = wtot[0] + wtot[1] + wtot[2] + wtot[3];
    __syncthreads();
    const int cnt = s_cnt;

    if (cnt == 0) {
        if (t < 64) {
            int oi = t >> 4, oj = (t >> 2) & 3, ok = t & 3;
            out[((bi * SS + oi) * RES + (bj * SS + oj)) * RES + (bk * SS + ok)] = 0.0f;
        }
        return;
    }

    // thread role: column (x,y) + split id
    const int col = lane & 15;             // 0..15
    const int h   = lane >> 4;             // half-warp
    const int sid = wi * 2 + h;            // split 0..15
    const int oi  = col >> 2, oj = col & 3;

    const float px  = -1.0f + STEP * (float)(bi * SS + oi);
    const float py  = -1.0f + STEP * (float)(bj * SS + oj);
    const float pz0 = -1.0f + STEP * (float)(bk * SS);
    const float pz1 = -1.0f + STEP * (float)(bk * SS + 1);
    const float pz2 = -1.0f + STEP * (float)(bk * SS + 2);
    const float pz3 = -1.0f + STEP * (float)(bk * SS + 3);

    const float4* __restrict__ par = g_par;

    float ac0 = 0.0f, ac1 = 0.0f, ac2 = 0.0f, ac3 = 0.0f;

#pragma unroll 2
    for (int j = sid; j < cnt; j += 16) {
        int g = list[j];
        float4 A = par[3 * g];
        float4 B = par[3 * g + 1];
        float4 C = par[3 * g + 2];
        float dx = px - A.x, dy = py - A.y;
        // c0 = q0*dx^2 + q1*dx*dy + q3*dy^2 ; c1 = q2*dx + q4*dy ; c2 = q5
        float t0 = fmaf(B.y, dy, B.x * dx);
        float c0 = fmaf(B.w * dy, dy, dx * t0);
        float c1 = fmaf(C.x, dy, B.z * dx);
        float c2 = C.y;
        float w  = A.w;

        float dz, p, ex;
        dz = pz0 - A.z; p = fmaf(fmaf(c2, dz, c1), dz, c0);
        ex = exp2f(p); if (p <= 0.0f) ac0 = fmaf(w, ex, ac0);
        dz = pz1 - A.z; p = fmaf(fmaf(c2, dz, c1), dz, c0);
        ex = exp2f(p); if (p <= 0.0f) ac1 = fmaf(w, ex, ac1);
        dz = pz2 - A.z; p = fmaf(fmaf(c2, dz, c1), dz, c0);
        ex = exp2f(p); if (p <= 0.0f) ac2 = fmaf(w, ex, ac2);
        dz = pz3 - A.z; p = fmaf(fmaf(c2, dz, c1), dz, c0);
        ex = exp2f(p); if (p <= 0.0f) ac3 = fmaf(w, ex, ac3);
    }

    // red[sid][col*4 + k]  — conflict-free vector store
    *reinterpret_cast<float4*>(&red[sid][col * 4]) = make_float4(ac0, ac1, ac2, ac3);
    __syncthreads();

    if (t < 64) {
        float s = 0.0f;
#pragma unroll
        for (int k = 0; k < 16; k++) s += red[k][t];
        int oi2 = t >> 4, oj2 = (t >> 2) & 3, ok2 = t & 3;
        out[((bi * SS + oi2) * RES + (bj * SS + oj2)) * RES + (bk * SS + ok2)] = s;
    }
}

// ============================================================
extern "C" void kernel_launch(void* const* d_in, const int* in_sizes, int n_in,
                              void* d_out, int out_size) {
    const float* xyz     = (const float*)d_in[0];
    const float* scaling = (const float*)d_in[1];
    const float* rot     = (const float*)d_in[2];
    const float* opac    = (const float*)d_in[3];
    float* out = (float*)d_out;

    kA<<<NW, 128>>>(xyz, scaling, rot, opac);
    kmain<<<NB * NB * NB, 256>>>(out);
}